// round 1
// baseline (speedup 1.0000x reference)
#include <cuda_runtime.h>
#include <math.h>

#define Bq   128
#define Sq   256
#define DMq  128
#define Hq   8
#define DKq  16
#define NTOPq 30
#define SKq  30
#define KSq  7

// ---------------- scratch (device globals; no allocations allowed) -------------
__device__ float g_qrot [Bq*Sq*DMq];
__device__ float g_krot [Bq*Sq*DMq];
__device__ float g_kconv[Bq*Sq*DMq];
__device__ float g_vconv[Bq*Sq*DMq];
__device__ float g_ctx  [Bq*Sq*DMq];
__device__ float g_cos  [Sq*64];
__device__ float g_sin  [Sq*64];
__device__ int   g_mtop [Bq*Hq*NTOPq];

// ---------------- trig table: match JAX's fp32 rounding structure --------------
// freqs = 1.0f / (float)(10000.0 ** (2i/128))  (powf correctly rounded via double)
// ang   = (float)s * freq   (fp32 multiply, matches XLA)
// cos/sin evaluated correctly-rounded (double) at the fp32 angle.
__global__ void trig_kernel() {
    int idx = blockIdx.x * blockDim.x + threadIdx.x;
    if (idx >= Sq * 64) return;
    int s = idx >> 6, i = idx & 63;
    double p  = pow(10000.0, (double)(2 * i) / 128.0);
    float  pf = (float)p;
    float  freq = 1.0f / pf;
    float  ang  = (float)s * freq;
    g_cos[idx] = (float)cos((double)ang);
    g_sin[idx] = (float)sin((double)ang);
}

// ---------------- rotary on q and k --------------------------------------------
__global__ void rotary_kernel(const float* __restrict__ q, const float* __restrict__ k) {
    int idx = blockIdx.x * blockDim.x + threadIdx.x;
    if (idx >= Bq * Sq * 64) return;
    int i  = idx & 63;
    int bs = idx >> 6;
    int s  = bs & (Sq - 1);
    float c  = g_cos[s * 64 + i];
    float sn = g_sin[s * 64 + i];
    size_t base = (size_t)bs * DMq + 2 * i;
    float q0 = q[base], q1 = q[base + 1];
    g_qrot[base]     = q0 * c - q1 * sn;
    g_qrot[base + 1] = q0 * sn + q1 * c;
    float k0 = k[base], k1 = k[base + 1];
    g_krot[base]     = k0 * c - k1 * sn;
    g_krot[base + 1] = k0 * sn + k1 * c;
}

// ---------------- causal "conv" = shifted GEMM ----------------------------------
// y[b,so,d] = bias[so] + sum_{si=0..255} sum_{t=0..6} w[so,si,t] * x[b,si,d+t-6]
// Block: (so-tile of 64) x (all 128 d) for one b. 256 threads, 4x8 reg tile.
// which==0: x = g_krot, y = g_kconv;  which==1: x = xin (raw value), y = g_vconv.
__global__ void conv_kernel(int which, const float* __restrict__ xin,
                            const float* __restrict__ w, const float* __restrict__ bias) {
    __shared__ float xs[8][136];
    __shared__ float ws[8][7][65];   // padded to kill 32-way bank conflicts on store
    int b   = blockIdx.y;
    int so0 = blockIdx.x * 64;
    int tid = threadIdx.x;
    int tx  = tid & 15;   // d group
    int ty  = tid >> 4;   // so group (0..15)

    const float* x = (which == 0) ? (const float*)g_krot : xin;
    float*       y = (which == 0) ? g_kconv : g_vconv;

    float acc[4][8];
#pragma unroll
    for (int r = 0; r < 4; r++)
#pragma unroll
        for (int c = 0; c < 8; c++) acc[r][c] = 0.f;

    const float* xb = x + (size_t)b * Sq * DMq;

    for (int si0 = 0; si0 < Sq; si0 += 8) {
        __syncthreads();
        // x tile: xs[sl][dp] = x[b, si0+sl, dp-6] (zero-pad left)
        for (int idx = tid; idx < 8 * 136; idx += 256) {
            int sl = idx / 136;
            int dp = idx - sl * 136;
            int d  = dp - 6;
            xs[sl][dp] = (d >= 0 && d < DMq) ? xb[(size_t)(si0 + sl) * DMq + d] : 0.f;
        }
        // w tile: ws[sl][t][sol] = w[so0+sol, si0+sl, t]
        for (int idx = tid; idx < 8 * 7 * 64; idx += 256) {
            int sol = idx / 56;
            int rem = idx - sol * 56;
            int sl  = rem / 7;
            int t   = rem - sl * 7;
            ws[sl][t][sol] = w[((size_t)(so0 + sol) * Sq + (si0 + sl)) * KSq + t];
        }
        __syncthreads();
#pragma unroll
        for (int sl = 0; sl < 8; sl++) {
#pragma unroll
            for (int t = 0; t < 7; t++) {
                float wv0 = ws[sl][t][ty];
                float wv1 = ws[sl][t][ty + 16];
                float wv2 = ws[sl][t][ty + 32];
                float wv3 = ws[sl][t][ty + 48];
                float xv[8];
#pragma unroll
                for (int c = 0; c < 8; c++) xv[c] = xs[sl][tx + 16 * c + t];
#pragma unroll
                for (int c = 0; c < 8; c++) {
                    acc[0][c] += wv0 * xv[c];
                    acc[1][c] += wv1 * xv[c];
                    acc[2][c] += wv2 * xv[c];
                    acc[3][c] += wv3 * xv[c];
                }
            }
        }
    }
#pragma unroll
    for (int r = 0; r < 4; r++) {
        int so = so0 + ty + 16 * r;
        float bv = bias[so];
#pragma unroll
        for (int c = 0; c < 8; c++)
            y[((size_t)b * Sq + so) * DMq + tx + 16 * c] = acc[r][c] + bv;
    }
}

// ---------------- fill context with per-(b,h,d) mean of v -----------------------
__global__ void fill_kernel() {
    int b  = blockIdx.x;
    int dm = threadIdx.x;   // 0..127
    const float* vb = g_vconv + (size_t)b * Sq * DMq + dm;
    float ssum = 0.f;
    for (int s = 0; s < Sq; s++) ssum += vb[(size_t)s * DMq];
    float mean = ssum * (1.0f / 256.0f);
    float* xb = g_ctx + (size_t)b * Sq * DMq + dm;
    for (int s = 0; s < Sq; s++) xb[(size_t)s * DMq] = mean;
}

// ---------------- sampled QK, M = max - mean, top-30 selection ------------------
__global__ void sample_topk_kernel(const int* __restrict__ idxs) {
    int bh = blockIdx.x;
    int b  = bh >> 3, h = bh & 7;
    int l  = threadIdx.x;  // 0..255

    __shared__ float Msh[256];
    __shared__ float rv[256];
    __shared__ int   ri[256];

    const float4* qp = reinterpret_cast<const float4*>(
        g_qrot + ((size_t)b * Sq + l) * DMq + h * DKq);
    float4 q0 = qp[0], q1 = qp[1], q2 = qp[2], q3 = qp[3];

    float mx = -3.402823466e38f;
    float sum = 0.f;
    for (int s = 0; s < SKq; s++) {
        int j = idxs[l * SKq + s];
        const float4* kp = reinterpret_cast<const float4*>(
            g_kconv + ((size_t)b * Sq + j) * DMq + h * DKq);
        float4 k0 = kp[0], k1 = kp[1], k2 = kp[2], k3 = kp[3];
        float dot = 0.f;
        dot += q0.x * k0.x; dot += q0.y * k0.y; dot += q0.z * k0.z; dot += q0.w * k0.w;
        dot += q1.x * k1.x; dot += q1.y * k1.y; dot += q1.z * k1.z; dot += q1.w * k1.w;
        dot += q2.x * k2.x; dot += q2.y * k2.y; dot += q2.z * k2.z; dot += q2.w * k2.w;
        dot += q3.x * k3.x; dot += q3.y * k3.y; dot += q3.z * k3.z; dot += q3.w * k3.w;
        mx = fmaxf(mx, dot);
        sum += dot;
    }
    Msh[l] = mx - sum * (1.0f / 30.0f);
    __syncthreads();

    // 30 rounds of argmax (ties -> lowest index, matching lax.top_k)
    for (int u = 0; u < NTOPq; u++) {
        rv[l] = Msh[l];
        ri[l] = l;
        __syncthreads();
        for (int stp = 128; stp > 0; stp >>= 1) {
            if (l < stp) {
                float v2 = rv[l + stp];
                int   i2 = ri[l + stp];
                if (v2 > rv[l] || (v2 == rv[l] && i2 < ri[l])) { rv[l] = v2; ri[l] = i2; }
            }
            __syncthreads();
        }
        if (l == 0) {
            g_mtop[bh * NTOPq + u] = ri[0];
            Msh[ri[0]] = -3.402823466e38f;
        }
        __syncthreads();
    }
}

// ---------------- full attention for the selected rows, scatter into context ----
__global__ void attend_kernel() {
    int u  = blockIdx.x;
    int bh = blockIdx.y;
    int b  = bh >> 3, h = bh & 7;
    int l  = threadIdx.x;   // key position 0..255
    int lsel = g_mtop[bh * NTOPq + u];

    __shared__ float p[256];
    __shared__ float red[256];
    __shared__ float qsh[16];

    if (l < 16)
        qsh[l] = g_qrot[((size_t)b * Sq + lsel) * DMq + h * DKq + l];
    __syncthreads();

    const float4* kp = reinterpret_cast<const float4*>(
        g_kconv + ((size_t)b * Sq + l) * DMq + h * DKq);
    float dot = 0.f;
#pragma unroll
    for (int j = 0; j < 4; j++) {
        float4 kv = kp[j];
        dot += qsh[4 * j + 0] * kv.x;
        dot += qsh[4 * j + 1] * kv.y;
        dot += qsh[4 * j + 2] * kv.z;
        dot += qsh[4 * j + 3] * kv.w;
    }
    float score = dot * 0.25f;   // / sqrt(16)

    red[l] = score; __syncthreads();
    for (int stp = 128; stp > 0; stp >>= 1) {
        if (l < stp) red[l] = fmaxf(red[l], red[l + stp]);
        __syncthreads();
    }
    float mxv = red[0];
    __syncthreads();

    float e = expf(score - mxv);
    p[l]   = e;
    red[l] = e;
    __syncthreads();
    for (int stp = 128; stp > 0; stp >>= 1) {
        if (l < stp) red[l] += red[l + stp];
        __syncthreads();
    }
    float inv = 1.0f / red[0];
    __syncthreads();

    if (l < 16) {
        const float* vb = g_vconv + (size_t)b * Sq * DMq + h * DKq + l;
        float o = 0.f;
        for (int ll = 0; ll < 256; ll++) o += p[ll] * vb[(size_t)ll * DMq];
        g_ctx[((size_t)b * Sq + lsel) * DMq + h * DKq + l] = o * inv;
    }
}

// ---------------- final linear: out = x @ W^T + b --------------------------------
__global__ void linear_kernel(const float* __restrict__ w, const float* __restrict__ bias,
                              float* __restrict__ out) {
    __shared__ float xsh[8][68];    // [i_local][row_local], padded
    __shared__ float wsh[8][132];   // [i_local][j], padded
    int r0  = blockIdx.x * 64;
    int tid = threadIdx.x;
    int tx  = tid & 15;   // j group
    int ty  = tid >> 4;   // row group

    float acc[4][8];
#pragma unroll
    for (int r = 0; r < 4; r++)
#pragma unroll
        for (int c = 0; c < 8; c++) acc[r][c] = 0.f;

    for (int i0 = 0; i0 < DMq; i0 += 8) {
        __syncthreads();
        // coalesced: il fastest
        for (int idx = tid; idx < 8 * 64; idx += 256) {
            int il = idx & 7, rl = idx >> 3;
            xsh[il][rl] = g_ctx[(size_t)(r0 + rl) * DMq + i0 + il];
        }
        for (int idx = tid; idx < 8 * 128; idx += 256) {
            int il = idx & 7, j = idx >> 3;
            wsh[il][j] = w[(size_t)j * DMq + i0 + il];
        }
        __syncthreads();
#pragma unroll
        for (int il = 0; il < 8; il++) {
            float xv[4], wv[8];
#pragma unroll
            for (int r = 0; r < 4; r++) xv[r] = xsh[il][ty + 16 * r];
#pragma unroll
            for (int c = 0; c < 8; c++) wv[c] = wsh[il][tx + 16 * c];
#pragma unroll
            for (int r = 0; r < 4; r++)
#pragma unroll
                for (int c = 0; c < 8; c++) acc[r][c] += xv[r] * wv[c];
        }
    }
#pragma unroll
    for (int r = 0; r < 4; r++) {
        int row = r0 + ty + 16 * r;
#pragma unroll
        for (int c = 0; c < 8; c++) {
            int j = tx + 16 * c;
            out[(size_t)row * DMq + j] = acc[r][c] + bias[j];
        }
    }
}

// -------------------------------------------------------------------------------
extern "C" void kernel_launch(void* const* d_in, const int* in_sizes, int n_in,
                              void* d_out, int out_size) {
    const float* query = (const float*)d_in[0];
    const float* key   = (const float*)d_in[1];
    const float* value = (const float*)d_in[2];
    const float* ckw   = (const float*)d_in[3];
    const float* ckb   = (const float*)d_in[4];
    const float* cvw   = (const float*)d_in[5];
    const float* cvb   = (const float*)d_in[6];
    const float* lw    = (const float*)d_in[7];
    const float* lb    = (const float*)d_in[8];
    const int*   isamp = (const int*)d_in[9];
    float* out = (float*)d_out;

    trig_kernel<<<(Sq * 64 + 255) / 256, 256>>>();
    rotary_kernel<<<(Bq * Sq * 64 + 255) / 256, 256>>>(query, key);

    dim3 cgrid(4, Bq);
    conv_kernel<<<cgrid, 256>>>(0, (const float*)nullptr, ckw, ckb);  // k path (reads g_krot)
    conv_kernel<<<cgrid, 256>>>(1, value, cvw, cvb);                  // v path

    fill_kernel<<<Bq, 128>>>();
    sample_topk_kernel<<<Bq * Hq, 256>>>(isamp);

    dim3 agrid(NTOPq, Bq * Hq);
    attend_kernel<<<agrid, 256>>>();

    linear_kernel<<<(Bq * Sq) / 64, 256>>>(lw, lb, out);
}

// round 2
// speedup vs baseline: 1.8563x; 1.8563x over previous
#include <cuda_runtime.h>
#include <math.h>
#include <stdint.h>

#define Bq   128
#define Sq   256
#define DMq  128
#define Hq   8
#define DKq  16
#define NTOPq 30
#define SKq  30
#define KSq  7

// ---------------- scratch (device globals; no allocations allowed) -------------
__device__ float g_qrot [Bq*Sq*DMq];
__device__ float g_krot [Bq*Sq*DMq];
__device__ float g_kconv[Bq*Sq*DMq];
__device__ float g_vconv[Bq*Sq*DMq];
__device__ float g_ctx  [Bq*Sq*DMq];
__device__ float g_cos  [Sq*64];
__device__ float g_sin  [Sq*64];
__device__ int   g_mtop [Bq*Hq*NTOPq];

// ---------------- trig table: match JAX's fp32 rounding structure --------------
__global__ void trig_kernel() {
    int idx = blockIdx.x * blockDim.x + threadIdx.x;
    if (idx >= Sq * 64) return;
    int s = idx >> 6, i = idx & 63;
    double p  = pow(10000.0, (double)(2 * i) / 128.0);
    float  pf = (float)p;
    float  freq = 1.0f / pf;
    float  ang  = (float)s * freq;
    g_cos[idx] = (float)cos((double)ang);
    g_sin[idx] = (float)sin((double)ang);
}

// ---------------- rotary on q and k --------------------------------------------
__global__ void rotary_kernel(const float* __restrict__ q, const float* __restrict__ k) {
    int idx = blockIdx.x * blockDim.x + threadIdx.x;
    if (idx >= Bq * Sq * 64) return;
    int i  = idx & 63;
    int bs = idx >> 6;
    int s  = bs & (Sq - 1);
    float c  = g_cos[s * 64 + i];
    float sn = g_sin[s * 64 + i];
    size_t base = (size_t)bs * DMq + 2 * i;
    float q0 = q[base], q1 = q[base + 1];
    g_qrot[base]     = q0 * c - q1 * sn;
    g_qrot[base + 1] = q0 * sn + q1 * c;
    float k0 = k[base], k1 = k[base + 1];
    g_krot[base]     = k0 * c - k1 * sn;
    g_krot[base + 1] = k0 * sn + k1 * c;
}

// ---------------- packed fp32 helpers -------------------------------------------
__device__ __forceinline__ void fma2(unsigned long long& acc, unsigned long long a,
                                     unsigned long long b) {
    asm("fma.rn.f32x2 %0, %1, %2, %0;" : "+l"(acc) : "l"(a), "l"(b));
}
__device__ __forceinline__ unsigned long long bcast2(float x) {
    unsigned long long r;
    asm("mov.b64 %0, {%1, %1};" : "=l"(r) : "f"(x));
    return r;
}
__device__ __forceinline__ void unpack2(unsigned long long v, float& lo, float& hi) {
    asm("mov.b64 {%0, %1}, %2;" : "=f"(lo), "=f"(hi) : "l"(v));
}

#define CP_ASYNC4(dst_u32, src_ptr) \
    asm volatile("cp.async.ca.shared.global [%0], [%1], 4;" :: "r"(dst_u32), "l"(src_ptr))
#define CP_COMMIT()  asm volatile("cp.async.commit_group;")
#define CP_WAIT1()   asm volatile("cp.async.wait_group 1;")
#define CP_WAIT0()   asm volatile("cp.async.wait_group 0;")

// ---------------- causal "conv" = shifted GEMM, f32x2 packed --------------------
// y[b,so,d] = bias[so] + sum_{si,t} w[so,si,t] * x[b,si,d+t-6]
// Block tile: 64 so x 128 d for one b. z=0: x=g_krot,y=g_kconv; z=1: x=value,y=g_vconv
// Threads: 256 = tx(32, d) x ty(8, so). Per-thread tile: 8 so (4 f32x2 pairs) x 4 d.
__global__ void __launch_bounds__(256, 2)
conv2_kernel(const float* __restrict__ vin,
             const float* __restrict__ wk, const float* __restrict__ bk,
             const float* __restrict__ wv, const float* __restrict__ bv) {
    __shared__ __align__(16) float xs[2][8][136];
    __shared__ __align__(16) float ws[2][56][68];

    const int b   = blockIdx.y;
    const int so0 = blockIdx.x * 64;
    const int z   = blockIdx.z;
    const int tid = threadIdx.x;
    const int tx  = tid & 31;
    const int ty  = tid >> 5;
    const int tx4 = tx * 4;
    const int ty8 = ty * 8;

    const float* __restrict__ w    = (z == 0) ? wk : wv;
    const float* __restrict__ bias = (z == 0) ? bk : bv;
    const float* __restrict__ xb   = ((z == 0) ? (const float*)g_krot : vin) + (size_t)b * Sq * DMq;
    float* __restrict__ yb         = ((z == 0) ? g_kconv : g_vconv) + (size_t)b * Sq * DMq;

    // smem u32 bases
    const uint32_t xs_base = (uint32_t)__cvta_generic_to_shared(&xs[0][0][0]);
    const uint32_t ws_base = (uint32_t)__cvta_generic_to_shared(&ws[0][0][0]);
    const uint32_t xs_buf_bytes = 8 * 136 * 4;
    const uint32_t ws_buf_bytes = 56 * 68 * 4;

    // ---- staging maps (affine, division-free) ----
    // x: warp = row sl (tid>>5), dp = lane + 32k (k=0..4), valid 6<=dp<134
    const int x_sl   = ty;                 // 0..7
    const int x_lane = tx;
    // w: sol = tid>>2 (0..63), stl = (tid&3)*14 + k (k=0..13)
    const int w_sol  = tid >> 2;
    const int w_stl0 = (tid & 3) * 14;
    const long w_goff0 = (long)(so0 + w_sol) * (Sq * KSq) + w_stl0;  // + si0*7 + k
    const uint32_t w_soff0 = ws_base + (uint32_t)(w_stl0 * 68 + w_sol) * 4; // + buf + 272k

    // zero the permanent-zero x halo cells (both buffers)
    if (tid < 128) {
        int buf = tid >> 6;
        int r   = tid & 63;
        int sl  = r >> 3;
        int j   = r & 7;
        int dp  = (j < 6) ? j : (128 + j);
        xs[buf][sl][dp] = 0.0f;
    }

    unsigned long long acc[4][4];
#pragma unroll
    for (int p = 0; p < 4; p++)
#pragma unroll
        for (int c = 0; c < 4; c++) acc[p][c] = 0ULL;

    // ---- issue tile 0 ----
    {
        const int si0 = 0;
        // x
#pragma unroll
        for (int k = 0; k < 5; k++) {
            int dp = x_lane + 32 * k;
            if (dp >= 6 && dp < 134) {
                uint32_t dst = xs_base + (uint32_t)(x_sl * 136 + dp) * 4;
                CP_ASYNC4(dst, xb + (size_t)(si0 + x_sl) * DMq + dp - 6);
            }
        }
        // w
#pragma unroll
        for (int k = 0; k < 14; k++) {
            uint32_t dst = w_soff0 + (uint32_t)(272 * k);
            CP_ASYNC4(dst, w + w_goff0 + (long)si0 * 7 + k);
        }
        CP_COMMIT();
    }

#pragma unroll 1
    for (int it = 0; it < 32; it++) {
        const int cur = it & 1;
        if (it < 31) {
            const int si0 = (it + 1) * 8;
            const int nxt = cur ^ 1;
            const uint32_t xoff = xs_base + nxt * xs_buf_bytes;
            const uint32_t woff = w_soff0 + nxt * ws_buf_bytes;
#pragma unroll
            for (int k = 0; k < 5; k++) {
                int dp = x_lane + 32 * k;
                if (dp >= 6 && dp < 134) {
                    uint32_t dst = xoff + (uint32_t)(x_sl * 136 + dp) * 4;
                    CP_ASYNC4(dst, xb + (size_t)(si0 + x_sl) * DMq + dp - 6);
                }
            }
#pragma unroll
            for (int k = 0; k < 14; k++) {
                uint32_t dst = woff + (uint32_t)(272 * k);
                CP_ASYNC4(dst, w + w_goff0 + (long)si0 * 7 + k);
            }
            CP_COMMIT();
            CP_WAIT1();
        } else {
            CP_WAIT0();
        }
        __syncthreads();   // tile `cur` visible to all

        // ---- compute on buffer cur ----
#pragma unroll
        for (int sl = 0; sl < 8; sl++) {
            const float4* xp = reinterpret_cast<const float4*>(&xs[cur][sl][tx4]);
            float4 a0 = xp[0], a1 = xp[1], a2 = xp[2];
            float xr[12] = {a0.x, a0.y, a0.z, a0.w,
                            a1.x, a1.y, a1.z, a1.w,
                            a2.x, a2.y, a2.z, a2.w};
#pragma unroll
            for (int t = 0; t < 7; t++) {
                const ulonglong2 wa = *reinterpret_cast<const ulonglong2*>(&ws[cur][sl*7 + t][ty8]);
                const ulonglong2 wb = *reinterpret_cast<const ulonglong2*>(&ws[cur][sl*7 + t][ty8 + 4]);
#pragma unroll
                for (int c = 0; c < 4; c++) {
                    unsigned long long xx = bcast2(xr[c + t]);
                    fma2(acc[0][c], wa.x, xx);
                    fma2(acc[1][c], wa.y, xx);
                    fma2(acc[2][c], wb.x, xx);
                    fma2(acc[3][c], wb.y, xx);
                }
            }
        }
        __syncthreads();   // all done reading cur before it gets overwritten
    }

    // ---- epilogue ----
#pragma unroll
    for (int p = 0; p < 4; p++) {
        float lo[4], hi[4];
#pragma unroll
        for (int c = 0; c < 4; c++) unpack2(acc[p][c], lo[c], hi[c]);
        int so = so0 + ty8 + 2 * p;
        float b0 = bias[so], b1 = bias[so + 1];
        float4 v0 = make_float4(lo[0] + b0, lo[1] + b0, lo[2] + b0, lo[3] + b0);
        float4 v1 = make_float4(hi[0] + b1, hi[1] + b1, hi[2] + b1, hi[3] + b1);
        *reinterpret_cast<float4*>(&yb[(size_t)so * DMq + tx4])       = v0;
        *reinterpret_cast<float4*>(&yb[(size_t)(so + 1) * DMq + tx4]) = v1;
    }
}

// ---------------- fill context with per-(b,h,d) mean of v -----------------------
__global__ void fill_kernel() {
    int b  = blockIdx.x;
    int dm = threadIdx.x;
    const float* vb = g_vconv + (size_t)b * Sq * DMq + dm;
    float ssum = 0.f;
#pragma unroll 8
    for (int s = 0; s < Sq; s++) ssum += vb[(size_t)s * DMq];
    float mean = ssum * (1.0f / 256.0f);
    float* xb = g_ctx + (size_t)b * Sq * DMq + dm;
#pragma unroll 8
    for (int s = 0; s < Sq; s++) xb[(size_t)s * DMq] = mean;
}

// ---------------- sampled QK, M = max - mean, top-30 (warp-shuffle select) ------
__global__ void sample_topk_kernel(const int* __restrict__ idxs) {
    int bh = blockIdx.x;
    int b  = bh >> 3, h = bh & 7;
    int l  = threadIdx.x;  // 0..255

    __shared__ float Msh[256];

    const float4* qp = reinterpret_cast<const float4*>(
        g_qrot + ((size_t)b * Sq + l) * DMq + h * DKq);
    float4 q0 = qp[0], q1 = qp[1], q2 = qp[2], q3 = qp[3];

    float mx = -3.402823466e38f;
    float sum = 0.f;
    for (int s = 0; s < SKq; s++) {
        int j = idxs[l * SKq + s];
        const float4* kp = reinterpret_cast<const float4*>(
            g_kconv + ((size_t)b * Sq + j) * DMq + h * DKq);
        float4 k0 = kp[0], k1 = kp[1], k2 = kp[2], k3 = kp[3];
        float dot = 0.f;
        dot += q0.x * k0.x; dot += q0.y * k0.y; dot += q0.z * k0.z; dot += q0.w * k0.w;
        dot += q1.x * k1.x; dot += q1.y * k1.y; dot += q1.z * k1.z; dot += q1.w * k1.w;
        dot += q2.x * k2.x; dot += q2.y * k2.y; dot += q2.z * k2.z; dot += q2.w * k2.w;
        dot += q3.x * k3.x; dot += q3.y * k3.y; dot += q3.z * k3.z; dot += q3.w * k3.w;
        mx = fmaxf(mx, dot);
        sum += dot;
    }
    Msh[l] = mx - sum * (1.0f / 30.0f);
    __syncthreads();

    // warp 0 selects top-30 via shuffles (ties -> lowest index, matching lax.top_k)
    if (l < 32) {
        float mv[8];
#pragma unroll
        for (int j = 0; j < 8; j++) mv[j] = Msh[l + 32 * j];
#pragma unroll 1
        for (int u = 0; u < NTOPq; u++) {
            float bvv = mv[0];
            int   bj  = 0;
#pragma unroll
            for (int j = 1; j < 8; j++)
                if (mv[j] > bvv) { bvv = mv[j]; bj = j; }
            int bidx = l + 32 * bj;   // within-thread: larger j = larger idx; strict > keeps lowest
#pragma unroll
            for (int off = 16; off > 0; off >>= 1) {
                float ov = __shfl_xor_sync(0xffffffffu, bvv, off);
                int   oi = __shfl_xor_sync(0xffffffffu, bidx, off);
                if (ov > bvv || (ov == bvv && oi < bidx)) { bvv = ov; bidx = oi; }
            }
            if (l == 0) g_mtop[bh * NTOPq + u] = bidx;
            if ((bidx & 31) == l) {
                int slot = bidx >> 5;
#pragma unroll
                for (int j = 0; j < 8; j++)
                    if (j == slot) mv[j] = -3.402823466e38f;
            }
        }
    }
}

// ---------------- attention for selected rows, one block per (b,h) --------------
__global__ void attend_kernel() {
    int bh = blockIdx.x;
    int b  = bh >> 3, h = bh & 7;
    int tid = threadIdx.x;

    __shared__ float ksh[256 * 17];
    __shared__ float vsh[256 * 17];
    __shared__ float p[256];
    __shared__ float wredM[8];
    __shared__ float wredS[8];
    __shared__ float part[16 * 17];
    __shared__ float qsh[16];

    // stage K and V tiles (256 x 16), padded rows
#pragma unroll
    for (int k = 0; k < 16; k++) {
        int idx = tid + 256 * k;
        int row = idx >> 4, d = idx & 15;
        size_t g = ((size_t)b * Sq + row) * DMq + h * DKq + d;
        ksh[row * 17 + d] = g_kconv[g];
        vsh[row * 17 + d] = g_vconv[g];
    }
    __syncthreads();

    const int warp = tid >> 5;
    const int dloc = tid & 15;
    const int seg  = tid >> 4;

#pragma unroll 1
    for (int u = 0; u < NTOPq; u++) {
        int lsel = g_mtop[bh * NTOPq + u];
        if (tid < 16)
            qsh[tid] = g_qrot[((size_t)b * Sq + lsel) * DMq + h * DKq + tid];
        __syncthreads();                                   // A

        float dot = 0.f;
#pragma unroll
        for (int j = 0; j < 16; j++) dot += qsh[j] * ksh[tid * 17 + j];
        float sc = dot * 0.25f;

        float wm = sc;
#pragma unroll
        for (int off = 16; off > 0; off >>= 1)
            wm = fmaxf(wm, __shfl_xor_sync(0xffffffffu, wm, off));
        if ((tid & 31) == 0) wredM[warp] = wm;
        __syncthreads();                                   // B
        float m = wredM[0];
#pragma unroll
        for (int j = 1; j < 8; j++) m = fmaxf(m, wredM[j]);

        float e = expf(sc - m);
        p[tid] = e;
        float wsum = e;
#pragma unroll
        for (int off = 16; off > 0; off >>= 1)
            wsum += __shfl_xor_sync(0xffffffffu, wsum, off);
        if ((tid & 31) == 0) wredS[warp] = wsum;
        __syncthreads();                                   // C

        // partial output: seg covers 16 keys, dloc is head dim
        float o = 0.f;
        int base = seg * 16;
#pragma unroll
        for (int ll = 0; ll < 16; ll++)
            o += p[base + ll] * vsh[(base + ll) * 17 + dloc];
        part[seg * 17 + dloc] = o;
        __syncthreads();                                   // D

        if (tid < 16) {
            float s = wredS[0];
#pragma unroll
            for (int j = 1; j < 8; j++) s += wredS[j];
            float inv = 1.0f / s;
            float oo = 0.f;
#pragma unroll
            for (int sg = 0; sg < 16; sg++) oo += part[sg * 17 + tid];
            g_ctx[((size_t)b * Sq + lsel) * DMq + h * DKq + tid] = oo * inv;
        }
        // no extra sync needed: only tid<16 write qsh next iter, after their writes here;
        // p/wred are rewritten only after barriers A/B of the next iteration.
    }
}

// ---------------- final linear: out = x @ W^T + b --------------------------------
__global__ void linear_kernel(const float* __restrict__ w, const float* __restrict__ bias,
                              float* __restrict__ out) {
    __shared__ float xsh[8][68];
    __shared__ float wsh[8][132];
    int r0  = blockIdx.x * 64;
    int tid = threadIdx.x;
    int tx  = tid & 15;
    int ty  = tid >> 4;

    float acc[4][8];
#pragma unroll
    for (int r = 0; r < 4; r++)
#pragma unroll
        for (int c = 0; c < 8; c++) acc[r][c] = 0.f;

    for (int i0 = 0; i0 < DMq; i0 += 8) {
        __syncthreads();
        for (int idx = tid; idx < 8 * 64; idx += 256) {
            int il = idx & 7, rl = idx >> 3;
            xsh[il][rl] = g_ctx[(size_t)(r0 + rl) * DMq + i0 + il];
        }
        for (int idx = tid; idx < 8 * 128; idx += 256) {
            int il = idx & 7, j = idx >> 3;
            wsh[il][j] = w[(size_t)j * DMq + i0 + il];
        }
        __syncthreads();
#pragma unroll
        for (int il = 0; il < 8; il++) {
            float xv[4], wv[8];
#pragma unroll
            for (int r = 0; r < 4; r++) xv[r] = xsh[il][ty + 16 * r];
#pragma unroll
            for (int c = 0; c < 8; c++) wv[c] = wsh[il][tx + 16 * c];
#pragma unroll
            for (int r = 0; r < 4; r++)
#pragma unroll
                for (int c = 0; c < 8; c++) acc[r][c] += xv[r] * wv[c];
        }
    }
#pragma unroll
    for (int r = 0; r < 4; r++) {
        int row = r0 + ty + 16 * r;
#pragma unroll
        for (int c = 0; c < 8; c++) {
            int j = tx + 16 * c;
            out[(size_t)row * DMq + j] = acc[r][c] + bias[j];
        }
    }
}

// -------------------------------------------------------------------------------
extern "C" void kernel_launch(void* const* d_in, const int* in_sizes, int n_in,
                              void* d_out, int out_size) {
    const float* query = (const float*)d_in[0];
    const float* key   = (const float*)d_in[1];
    const float* value = (const float*)d_in[2];
    const float* ckw   = (const float*)d_in[3];
    const float* ckb   = (const float*)d_in[4];
    const float* cvw   = (const float*)d_in[5];
    const float* cvb   = (const float*)d_in[6];
    const float* lw    = (const float*)d_in[7];
    const float* lb    = (const float*)d_in[8];
    const int*   isamp = (const int*)d_in[9];
    float* out = (float*)d_out;

    trig_kernel<<<(Sq * 64 + 255) / 256, 256>>>();
    rotary_kernel<<<(Bq * Sq * 64 + 255) / 256, 256>>>(query, key);

    dim3 cgrid(4, Bq, 2);
    conv2_kernel<<<cgrid, 256>>>(value, ckw, ckb, cvw, cvb);

    fill_kernel<<<Bq, 128>>>();
    sample_topk_kernel<<<Bq * Hq, 256>>>(isamp);
    attend_kernel<<<Bq * Hq, 256>>>();

    linear_kernel<<<(Bq * Sq) / 64, 256>>>(lw, lb, out);
}

// round 3
// speedup vs baseline: 2.1567x; 1.1618x over previous
#include <cuda_runtime.h>
#include <math.h>
#include <stdint.h>

#define Bq   128
#define Sq   256
#define DMq  128
#define Hq   8
#define DKq  16
#define NTOPq 30
#define SKq  30
#define KSq  7
#define KKq  (Sq*KSq)   // 1792

// ---------------- scratch (device globals; no allocations allowed) -------------
__device__ float g_qrot [Bq*Sq*DMq];
__device__ float g_krot [Bq*Sq*DMq];
__device__ float g_kconv[Bq*Sq*DMq];
__device__ float g_vconv[Bq*Sq*DMq];
__device__ float g_wT   [2*KKq*Sq];           // [z][kk][so]
__device__ float g_mean [Bq*DMq];
__device__ float g_ot   [Bq*Hq*NTOPq*DKq];
__device__ float g_cos  [Sq*64];
__device__ float g_sin  [Sq*64];
__device__ int   g_mtop [Bq*Hq*NTOPq];

// ---------------- trig table (exact double, tiny cost) --------------------------
__global__ void trig_kernel() {
    int idx = blockIdx.x * blockDim.x + threadIdx.x;
    if (idx >= Sq * 64) return;
    int s = idx >> 6, i = idx & 63;
    double p  = pow(10000.0, (double)(2 * i) / 128.0);
    float  pf = (float)p;
    float  freq = 1.0f / pf;
    float  ang  = (float)s * freq;
    g_cos[idx] = (float)cos((double)ang);
    g_sin[idx] = (float)sin((double)ang);
}

// ---------------- rotary on q and k --------------------------------------------
__global__ void rotary_kernel(const float* __restrict__ q, const float* __restrict__ k) {
    int idx = blockIdx.x * blockDim.x + threadIdx.x;
    if (idx >= Bq * Sq * 64) return;
    int i  = idx & 63;
    int bs = idx >> 6;
    int s  = bs & (Sq - 1);
    float c  = g_cos[s * 64 + i];
    float sn = g_sin[s * 64 + i];
    size_t base = (size_t)bs * DMq + 2 * i;
    float q0 = q[base], q1 = q[base + 1];
    g_qrot[base]     = q0 * c - q1 * sn;
    g_qrot[base + 1] = q0 * sn + q1 * c;
    float k0 = k[base], k1 = k[base + 1];
    g_krot[base]     = k0 * c - k1 * sn;
    g_krot[base + 1] = k0 * sn + k1 * c;
}

// ---------------- transpose w[so][kk] -> wT[kk][so] ------------------------------
__global__ void wtrans_kernel(const float* __restrict__ wk, const float* __restrict__ wv) {
    __shared__ float tile[32][33];
    const float* w = (blockIdx.z == 0) ? wk : wv;
    float* wt = g_wT + (size_t)blockIdx.z * KKq * Sq;
    int kk0 = blockIdx.x * 32;
    int so0 = blockIdx.y * 32;
    int tx = threadIdx.x, ty = threadIdx.y;   // (32, 8)
#pragma unroll
    for (int j = 0; j < 4; j++)
        tile[ty + 8 * j][tx] = w[(size_t)(so0 + ty + 8 * j) * KKq + kk0 + tx];
    __syncthreads();
#pragma unroll
    for (int j = 0; j < 4; j++)
        wt[(size_t)(kk0 + ty + 8 * j) * Sq + so0 + tx] = tile[tx][ty + 8 * j];
}

// ---------------- packed fp32 helpers -------------------------------------------
__device__ __forceinline__ void fma2(unsigned long long& acc, unsigned long long a,
                                     unsigned long long b) {
    asm("fma.rn.f32x2 %0, %1, %2, %0;" : "+l"(acc) : "l"(a), "l"(b));
}
__device__ __forceinline__ unsigned long long bcast2(float x) {
    unsigned long long r;
    asm("mov.b64 %0, {%1, %1};" : "=l"(r) : "f"(x));
    return r;
}
__device__ __forceinline__ void unpack2(unsigned long long v, float& lo, float& hi) {
    asm("mov.b64 {%0, %1}, %2;" : "=f"(lo), "=f"(hi) : "l"(v));
}

#define CP_ASYNC16(dst_u32, src_ptr) \
    asm volatile("cp.async.cg.shared.global [%0], [%1], 16;" :: "r"(dst_u32), "l"(src_ptr))
#define CP_COMMIT()  asm volatile("cp.async.commit_group;")
#define CP_WAIT1()   asm volatile("cp.async.wait_group 1;")
#define CP_WAIT0()   asm volatile("cp.async.wait_group 0;")

// ---------------- conv = shifted GEMM, f32x2, 128x128 tile ----------------------
// y[b,so,d] = bias[so] + sum_{kk=(si,t)} wT[kk,so] * x[b,si,d+t-6]
// grid (2 so-tiles, 128 b, 2 z); 256 threads = 32(tx:d) x 8(ty: 16-so groups)
// per-thread: 8 so-pairs (f32x2) x 4 d. Dynamic smem: xs[2][8][144] + ws[2][56][132]
#define XS_ROWPITCH 144
#define WS_ROWPITCH 132
#define XS_BUF_B (8*XS_ROWPITCH*4)       // 4608
#define WS_BUF_B (56*WS_ROWPITCH*4)      // 29568
#define CONV_SMEM (2*XS_BUF_B + 2*WS_BUF_B)  // 68352

__global__ void __launch_bounds__(256, 2)
conv3_kernel(const float* __restrict__ vin,
             const float* __restrict__ bk, const float* __restrict__ bv) {
    extern __shared__ __align__(16) char dsm[];
    float* sm = (float*)dsm;

    const int so0 = blockIdx.x * 128;
    const int b   = blockIdx.y;
    const int z   = blockIdx.z;
    const int tid = threadIdx.x;
    const int tx  = tid & 31;
    const int ty  = tid >> 5;
    const int tx4 = tx * 4;
    const int ty16 = ty * 16;

    const float* __restrict__ wz   = g_wT + (size_t)z * KKq * Sq;
    const float* __restrict__ bias = (z == 0) ? bk : bv;
    const float* __restrict__ xb   = ((z == 0) ? (const float*)g_krot : vin) + (size_t)b * Sq * DMq;
    float* __restrict__ yb         = ((z == 0) ? g_kconv : g_vconv) + (size_t)b * Sq * DMq;

    const uint32_t smb = (uint32_t)__cvta_generic_to_shared(sm);

    // staging maps
    const int st_row = tid >> 5;         // 0..7
    const int st_q   = tid & 31;         // 0..31 (float4 index)
    // x dst: xs[buf][st_row][8 + 4*st_q]
    const uint32_t x_dst0 = smb + (uint32_t)(st_row * XS_ROWPITCH + 8 + 4 * st_q) * 4;
    const float* x_src0 = xb + (size_t)st_row * DMq + 4 * st_q;

    // zero halo cells xs[buf][sl][0..7]
    if (tid < 128) {
        int buf = tid >> 6;
        int r   = tid & 63;
        int sl  = r >> 3;
        int j   = r & 7;
        sm[buf * (8 * XS_ROWPITCH) + sl * XS_ROWPITCH + j] = 0.0f;
    }

    unsigned long long acc[8][4];
#pragma unroll
    for (int p = 0; p < 8; p++)
#pragma unroll
        for (int c = 0; c < 4; c++) acc[p][c] = 0ULL;

    // ---- issue tile 0 ----
    {
        CP_ASYNC16(x_dst0, x_src0);
#pragma unroll
        for (int k = 0; k < 7; k++) {
            int idx = tid + 256 * k;
            int row = idx >> 5, q = idx & 31;
            uint32_t dst = smb + (uint32_t)(2 * 8 * XS_ROWPITCH + row * WS_ROWPITCH + 4 * q) * 4;
            CP_ASYNC16(dst, wz + (size_t)row * Sq + so0 + 4 * q);
        }
        CP_COMMIT();
    }

#pragma unroll 1
    for (int it = 0; it < 32; it++) {
        const int cur = it & 1;
        if (it < 31) {
            const int nxt = cur ^ 1;
            const int si0 = (it + 1) * 8;
            const int kk0 = (it + 1) * 56;
            CP_ASYNC16(x_dst0 + (uint32_t)(nxt * XS_BUF_B), x_src0 + (size_t)si0 * DMq);
#pragma unroll
            for (int k = 0; k < 7; k++) {
                int idx = tid + 256 * k;
                int row = idx >> 5, q = idx & 31;
                uint32_t dst = smb + (uint32_t)(2 * 8 * XS_ROWPITCH) * 4
                             + (uint32_t)(nxt * WS_BUF_B)
                             + (uint32_t)(row * WS_ROWPITCH + 4 * q) * 4;
                CP_ASYNC16(dst, wz + (size_t)(kk0 + row) * Sq + so0 + 4 * q);
            }
            CP_COMMIT();
            CP_WAIT1();
        } else {
            CP_WAIT0();
        }
        __syncthreads();

        const float* xsb = sm + cur * (8 * XS_ROWPITCH);
        const float* wsb = sm + 2 * 8 * XS_ROWPITCH + cur * (56 * WS_ROWPITCH);

#pragma unroll
        for (int sl = 0; sl < 8; sl++) {
            const float4* xp = reinterpret_cast<const float4*>(xsb + sl * XS_ROWPITCH + tx4);
            float4 a0 = xp[0], a1 = xp[1], a2 = xp[2], a3 = xp[3];
            float xw[16] = {a0.x, a0.y, a0.z, a0.w, a1.x, a1.y, a1.z, a1.w,
                            a2.x, a2.y, a2.z, a2.w, a3.x, a3.y, a3.z, a3.w};
#pragma unroll
            for (int t = 0; t < 7; t++) {
                const ulonglong2* wr = reinterpret_cast<const ulonglong2*>(
                    wsb + (sl * 7 + t) * WS_ROWPITCH + ty16);
                ulonglong2 wA = wr[0], wB = wr[1], wC = wr[2], wD = wr[3];
#pragma unroll
                for (int c = 0; c < 4; c++) {
                    unsigned long long xx = bcast2(xw[c + t + 2]);
                    fma2(acc[0][c], wA.x, xx);
                    fma2(acc[1][c], wA.y, xx);
                    fma2(acc[2][c], wB.x, xx);
                    fma2(acc[3][c], wB.y, xx);
                    fma2(acc[4][c], wC.x, xx);
                    fma2(acc[5][c], wC.y, xx);
                    fma2(acc[6][c], wD.x, xx);
                    fma2(acc[7][c], wD.y, xx);
                }
            }
        }
        __syncthreads();
    }

    // ---- epilogue ----
#pragma unroll
    for (int p = 0; p < 8; p++) {
        float lo[4], hi[4];
#pragma unroll
        for (int c = 0; c < 4; c++) unpack2(acc[p][c], lo[c], hi[c]);
        int so = so0 + ty16 + 2 * p;
        float b0 = bias[so], b1 = bias[so + 1];
        float4 v0 = make_float4(lo[0] + b0, lo[1] + b0, lo[2] + b0, lo[3] + b0);
        float4 v1 = make_float4(hi[0] + b1, hi[1] + b1, hi[2] + b1, hi[3] + b1);
        *reinterpret_cast<float4*>(&yb[(size_t)so * DMq + tx4])       = v0;
        *reinterpret_cast<float4*>(&yb[(size_t)(so + 1) * DMq + tx4]) = v1;
    }
}

// ---------------- per-(b,d) mean of vconv ---------------------------------------
__global__ void mean_kernel() {
    __shared__ float psum[8][DMq];
    int b  = blockIdx.x;
    int ty = threadIdx.x >> 5, q = threadIdx.x & 31;
    const float* vb = g_vconv + (size_t)b * Sq * DMq;
    float4 acc = make_float4(0.f, 0.f, 0.f, 0.f);
#pragma unroll 4
    for (int k = 0; k < 32; k++) {
        float4 v = *reinterpret_cast<const float4*>(vb + (size_t)(ty + 8 * k) * DMq + 4 * q);
        acc.x += v.x; acc.y += v.y; acc.z += v.z; acc.w += v.w;
    }
    *reinterpret_cast<float4*>(&psum[ty][4 * q]) = acc;
    __syncthreads();
    if (threadIdx.x < DMq) {
        float s = 0.f;
#pragma unroll
        for (int j = 0; j < 8; j++) s += psum[j][threadIdx.x];
        g_mean[b * DMq + threadIdx.x] = s * (1.0f / 256.0f);
    }
}

// ---------------- sampled QK, M = max - mean, top-30 ----------------------------
__global__ void sample_topk_kernel(const int* __restrict__ idxs) {
    int bh = blockIdx.x;
    int b  = bh >> 3, h = bh & 7;
    int l  = threadIdx.x;

    __shared__ float Msh[256];

    const float4* qp = reinterpret_cast<const float4*>(
        g_qrot + ((size_t)b * Sq + l) * DMq + h * DKq);
    float4 q0 = qp[0], q1 = qp[1], q2 = qp[2], q3 = qp[3];

    float mx = -3.402823466e38f;
    float sum = 0.f;
    for (int s = 0; s < SKq; s++) {
        int j = idxs[l * SKq + s];
        const float4* kp = reinterpret_cast<const float4*>(
            g_kconv + ((size_t)b * Sq + j) * DMq + h * DKq);
        float4 k0 = kp[0], k1 = kp[1], k2 = kp[2], k3 = kp[3];
        float dot = 0.f;
        dot += q0.x * k0.x; dot += q0.y * k0.y; dot += q0.z * k0.z; dot += q0.w * k0.w;
        dot += q1.x * k1.x; dot += q1.y * k1.y; dot += q1.z * k1.z; dot += q1.w * k1.w;
        dot += q2.x * k2.x; dot += q2.y * k2.y; dot += q2.z * k2.z; dot += q2.w * k2.w;
        dot += q3.x * k3.x; dot += q3.y * k3.y; dot += q3.z * k3.z; dot += q3.w * k3.w;
        mx = fmaxf(mx, dot);
        sum += dot;
    }
    Msh[l] = mx - sum * (1.0f / 30.0f);
    __syncthreads();

    if (l < 32) {
        float mv[8];
#pragma unroll
        for (int j = 0; j < 8; j++) mv[j] = Msh[l + 32 * j];
#pragma unroll 1
        for (int u = 0; u < NTOPq; u++) {
            float bvv = mv[0];
            int   bj  = 0;
#pragma unroll
            for (int j = 1; j < 8; j++)
                if (mv[j] > bvv) { bvv = mv[j]; bj = j; }
            int bidx = l + 32 * bj;
#pragma unroll
            for (int off = 16; off > 0; off >>= 1) {
                float ov = __shfl_xor_sync(0xffffffffu, bvv, off);
                int   oi = __shfl_xor_sync(0xffffffffu, bidx, off);
                if (ov > bvv || (ov == bvv && oi < bidx)) { bvv = ov; bidx = oi; }
            }
            if (l == 0) g_mtop[bh * NTOPq + u] = bidx;
            if ((bidx & 31) == l) {
                int slot = bidx >> 5;
#pragma unroll
                for (int j = 0; j < 8; j++)
                    if (j == slot) mv[j] = -3.402823466e38f;
            }
        }
    }
}

// ---------------- attention for selected rows, warp per row ---------------------
__global__ void attend_kernel() {
    __shared__ float ksh[256 * 17];
    __shared__ float vsh[256 * 17];
    int bh = blockIdx.x;
    int b  = bh >> 3, h = bh & 7;
    int tid = threadIdx.x;

#pragma unroll
    for (int k = 0; k < 16; k++) {
        int idx = tid + 256 * k;
        int row = idx >> 4, d = idx & 15;
        size_t g = ((size_t)b * Sq + row) * DMq + h * DKq + d;
        ksh[row * 17 + d] = g_kconv[g];
        vsh[row * 17 + d] = g_vconv[g];
    }
    __syncthreads();

    const int warp = tid >> 5;
    const int lane = tid & 31;

#pragma unroll 1
    for (int j = 0; j < 4; j++) {
        int u = warp + 8 * j;
        if (u >= NTOPq) break;
        int lsel = g_mtop[bh * NTOPq + u];
        float qv = g_qrot[((size_t)b * Sq + lsel) * DMq + h * DKq + (lane & 15)];

        float dot[8];
#pragma unroll
        for (int m = 0; m < 8; m++) dot[m] = 0.f;
#pragma unroll
        for (int i = 0; i < 16; i++) {
            float qi = __shfl_sync(0xffffffffu, qv, i);
#pragma unroll
            for (int m = 0; m < 8; m++)
                dot[m] += qi * ksh[(lane + 32 * m) * 17 + i];
        }
        float mx = -3.402823466e38f;
#pragma unroll
        for (int m = 0; m < 8; m++) { dot[m] *= 0.25f; mx = fmaxf(mx, dot[m]); }
#pragma unroll
        for (int off = 16; off > 0; off >>= 1)
            mx = fmaxf(mx, __shfl_xor_sync(0xffffffffu, mx, off));
        float p[8];
        float sum = 0.f;
#pragma unroll
        for (int m = 0; m < 8; m++) { p[m] = expf(dot[m] - mx); sum += p[m]; }
#pragma unroll
        for (int off = 16; off > 0; off >>= 1)
            sum += __shfl_xor_sync(0xffffffffu, sum, off);

        float o[16];
#pragma unroll
        for (int d = 0; d < 16; d++) o[d] = 0.f;
#pragma unroll
        for (int m = 0; m < 8; m++) {
            float pm = p[m];
            int base = (lane + 32 * m) * 17;
#pragma unroll
            for (int d = 0; d < 16; d++) o[d] += pm * vsh[base + d];
        }
#pragma unroll
        for (int off = 16; off > 0; off >>= 1)
#pragma unroll
            for (int d = 0; d < 16; d++)
                o[d] += __shfl_xor_sync(0xffffffffu, o[d], off);

        if (lane == 0) {
            float inv = 1.0f / sum;
            float* op = g_ot + ((size_t)bh * NTOPq + u) * DKq;
#pragma unroll
            for (int d4 = 0; d4 < 4; d4++) {
                float4 v = make_float4(o[4*d4]*inv, o[4*d4+1]*inv, o[4*d4+2]*inv, o[4*d4+3]*inv);
                *reinterpret_cast<float4*>(op + 4 * d4) = v;
            }
        }
    }
}

// ---------------- base output: out[b,s,:] = mean(b) @ W^T + bias ------------------
__global__ void base_kernel(const float* __restrict__ w, const float* __restrict__ bias,
                            float* __restrict__ out) {
    __shared__ float meansh[DMq];
    __shared__ float baseo[DMq];
    int b = blockIdx.x;
    int tid = threadIdx.x;
    if (tid < DMq) meansh[tid] = g_mean[b * DMq + tid];
    __syncthreads();
    if (tid < DMq) {
        const float4* wr = reinterpret_cast<const float4*>(w + (size_t)tid * DMq);
        float dot = 0.f;
#pragma unroll
        for (int q = 0; q < 32; q++) {
            float4 wv = wr[q];
            dot += wv.x * meansh[4*q] + wv.y * meansh[4*q+1]
                 + wv.z * meansh[4*q+2] + wv.w * meansh[4*q+3];
        }
        baseo[tid] = dot + bias[tid];
    }
    __syncthreads();
    const float4* b4 = reinterpret_cast<const float4*>(baseo);
    float4* o4 = reinterpret_cast<float4*>(out + (size_t)b * Sq * DMq);
#pragma unroll 4
    for (int k = 0; k < 32; k++) {
        int idx = tid + 256 * k;
        int s = idx >> 5, q = idx & 31;
        o4[s * 32 + q] = b4[q];
    }
}

// ---------------- scatter corrections: out[b,s,:] += (ot - mean_h) @ Wh^T --------
__global__ void scatter_kernel(const float* __restrict__ w, float* __restrict__ out) {
    int bh = blockIdx.x;
    int b  = bh >> 3, h = bh & 7;
    int j  = threadIdx.x;     // 0..127
    int lane = j & 31;

    // Wh[j][i] i=0..15
    float wh[16];
    const float4* wr = reinterpret_cast<const float4*>(w + (size_t)j * DMq + h * DKq);
#pragma unroll
    for (int q = 0; q < 4; q++) {
        float4 v = wr[q];
        wh[4*q] = v.x; wh[4*q+1] = v.y; wh[4*q+2] = v.z; wh[4*q+3] = v.w;
    }
    float msl = (lane < 16) ? g_mean[b * DMq + h * DKq + lane] : 0.f;
    float mi[16];
#pragma unroll
    for (int i = 0; i < 16; i++) mi[i] = __shfl_sync(0xffffffffu, msl, i);

#pragma unroll 1
    for (int u = 0; u < NTOPq; u++) {
        int s = g_mtop[bh * NTOPq + u];
        float otv = (lane < 16) ? g_ot[((size_t)bh * NTOPq + u) * DKq + lane] : 0.f;
        float corr = 0.f;
#pragma unroll
        for (int i = 0; i < 16; i++)
            corr += (__shfl_sync(0xffffffffu, otv, i) - mi[i]) * wh[i];
        atomicAdd(&out[((size_t)b * Sq + s) * DMq + j], corr);
    }
}

// -------------------------------------------------------------------------------
extern "C" void kernel_launch(void* const* d_in, const int* in_sizes, int n_in,
                              void* d_out, int out_size) {
    const float* query = (const float*)d_in[0];
    const float* key   = (const float*)d_in[1];
    const float* value = (const float*)d_in[2];
    const float* ckw   = (const float*)d_in[3];
    const float* ckb   = (const float*)d_in[4];
    const float* cvw   = (const float*)d_in[5];
    const float* cvb   = (const float*)d_in[6];
    const float* lw    = (const float*)d_in[7];
    const float* lb    = (const float*)d_in[8];
    const int*   isamp = (const int*)d_in[9];
    float* out = (float*)d_out;

    static int smem_set = 0;
    if (!smem_set) {
        cudaFuncSetAttribute(conv3_kernel, cudaFuncAttributeMaxDynamicSharedMemorySize,
                             CONV_SMEM);
        smem_set = 1;
    }

    trig_kernel<<<(Sq * 64 + 255) / 256, 256>>>();
    rotary_kernel<<<(Bq * Sq * 64 + 255) / 256, 256>>>(query, key);

    dim3 wtg(KKq / 32, Sq / 32, 2);
    wtrans_kernel<<<wtg, dim3(32, 8)>>>(ckw, cvw);

    dim3 cgrid(2, Bq, 2);
    conv3_kernel<<<cgrid, 256, CONV_SMEM>>>(value, ckb, cvb);

    mean_kernel<<<Bq, 256>>>();
    sample_topk_kernel<<<Bq * Hq, 256>>>(isamp);
    attend_kernel<<<Bq * Hq, 256>>>();

    base_kernel<<<Bq, 256>>>(lw, lb, out);
    scatter_kernel<<<Bq * Hq, 128>>>(lw, out);
}